// round 1
// baseline (speedup 1.0000x reference)
#include <cuda_runtime.h>

#define C 32
#define KT_MAX 125
#define EPSBN 1e-5f

// ---- device scratch (no allocations allowed) ----
__device__ __align__(16) float g_Wt[KT_MAX * C * C];   // [K][COUT][CIN]
__device__ float g_part[512 * 2 * C];                  // per-block partial sums / sumsq
__device__ float g_mean[C];
__device__ float g_rstd[C];

// ---------------- W transpose: [K][CIN][COUT] -> [K][COUT][CIN] ----------------
__global__ void transpose_w(const float* __restrict__ W, int total) {
    int i = blockIdx.x * blockDim.x + threadIdx.x;
    if (i < total) {
        int k = i / (C * C);
        int r = i % (C * C);
        int cin = r / C, cout = r % C;
        g_Wt[k * C * C + cout * C + cin] = W[i];
    }
}

// ---------------- sparse conv ----------------
#define VW 16                 // voxels per warp
#define WARPS 8
#define VB (VW * WARPS)       // voxels per block

__global__ __launch_bounds__(256) void conv_kernel(
    const float* __restrict__ x, const int* __restrict__ nbr,
    const float* __restrict__ bconv, float* __restrict__ out,
    int n, int kt)
{
    __shared__ __align__(16) float xsm[WARPS][VW][C];
    int warp = threadIdx.x >> 5, lane = threadIdx.x & 31;
    int v0 = blockIdx.x * VB + warp * VW;

    float b = bconv[lane];
    float acc[VW];
#pragma unroll
    for (int i = 0; i < VW; i++) acc[i] = b;

    for (int k = 0; k < kt; k++) {
        // per-lane weight column for this tap: Wt[k][lane][0..31], coalesced 128B/lane
        float4 w[8];
        const float4* wp = (const float4*)(g_Wt + k * C * C + lane * C);
#pragma unroll
        for (int j = 0; j < 8; j++) w[j] = wp[j];

        // stage valid gathered rows into smem (warp-uniform validity)
        unsigned vm = 0;
#pragma unroll
        for (int i = 0; i < VW; i++) {
            int v = v0 + i;
            if (v < n) {
                int idx = __ldg(&nbr[(long long)v * kt + k]);
                if (idx >= 0) {
                    vm |= (1u << i);
                    xsm[warp][i][lane] = x[idx * C + lane];
                }
            }
        }
        __syncwarp();

        // compute: per valid voxel 8x LDS.128 broadcast + 32 FFMA
#pragma unroll
        for (int i = 0; i < VW; i++) {
            if ((vm >> i) & 1u) {
                const float4* xs = (const float4*)xsm[warp][i];
                float a = acc[i];
#pragma unroll
                for (int j = 0; j < 8; j++) {
                    float4 xv = xs[j];
                    a = fmaf(xv.x, w[j].x, a);
                    a = fmaf(xv.y, w[j].y, a);
                    a = fmaf(xv.z, w[j].z, a);
                    a = fmaf(xv.w, w[j].w, a);
                }
                acc[i] = a;
            }
        }
        __syncwarp();
    }

#pragma unroll
    for (int i = 0; i < VW; i++) {
        int v = v0 + i;
        if (v < n) out[v * C + lane] = acc[i];
    }
}

// ---------------- BN stats: stage 1 (deterministic partials) ----------------
__global__ __launch_bounds__(256) void bn_partial(const float* __restrict__ out, int n) {
    int lane = threadIdx.x & 31, w = threadIdx.x >> 5;
    float s = 0.f, s2 = 0.f;
    for (int r = blockIdx.x * 8 + w; r < n; r += gridDim.x * 8) {
        float v = out[r * C + lane];
        s += v;
        s2 += v * v;
    }
    __shared__ float sh[2][8][C];
    sh[0][w][lane] = s;
    sh[1][w][lane] = s2;
    __syncthreads();
    if (threadIdx.x < C) {
        float S = 0.f, S2 = 0.f;
#pragma unroll
        for (int j = 0; j < 8; j++) { S += sh[0][j][threadIdx.x]; S2 += sh[1][j][threadIdx.x]; }
        g_part[blockIdx.x * 2 * C + threadIdx.x] = S;
        g_part[blockIdx.x * 2 * C + C + threadIdx.x] = S2;
    }
}

// ---------------- BN stats: stage 2 ----------------
__global__ void bn_final(int n, int nblocks) {
    int lane = threadIdx.x & 31, w = threadIdx.x >> 5;   // 256 threads, 8 warps
    float S = 0.f, S2 = 0.f;
    for (int b = w; b < nblocks; b += 8) {
        S  += g_part[b * 2 * C + lane];
        S2 += g_part[b * 2 * C + C + lane];
    }
    __shared__ float sh[2][8][C];
    sh[0][w][lane] = S;
    sh[1][w][lane] = S2;
    __syncthreads();
    if (threadIdx.x < C) {
        float a = 0.f, a2 = 0.f;
#pragma unroll
        for (int j = 0; j < 8; j++) { a += sh[0][j][threadIdx.x]; a2 += sh[1][j][threadIdx.x]; }
        float mean = a / (float)n;
        float var = a2 / (float)n - mean * mean;
        g_mean[threadIdx.x] = mean;
        g_rstd[threadIdx.x] = rsqrtf(var + EPSBN);
    }
}

// ---------------- BN apply + ELU + linear (in-place on out) ----------------
__global__ __launch_bounds__(256) void apply_kernel(
    const float* __restrict__ gamma, const float* __restrict__ beta,
    const float* __restrict__ Wlin, const float* __restrict__ blin,
    float* __restrict__ out, int n)
{
    __shared__ __align__(16) float ysm[WARPS][C];
    int lane = threadIdx.x & 31, w = threadIdx.x >> 5;
    float m = g_mean[lane], rs = g_rstd[lane];
    float ga = gamma[lane], be = beta[lane], bl = blin[lane];
    // z[o] = sum_c y[c] * Wlin[o][c] + bl[o]; per-lane row is contiguous
    float4 wl[8];
    const float4* wp = (const float4*)(Wlin + lane * C);
#pragma unroll
    for (int j = 0; j < 8; j++) wl[j] = wp[j];

    for (int v = blockIdx.x * 8 + w; v < n; v += gridDim.x * 8) {
        float o = out[v * C + lane];
        float y = fmaf((o - m) * rs, ga, be);
        y = (y > 0.f) ? y : expm1f(y);
        ysm[w][lane] = y;
        __syncwarp();
        const float4* ys = (const float4*)ysm[w];
        float z = bl;
#pragma unroll
        for (int j = 0; j < 8; j++) {
            float4 yv = ys[j];
            z = fmaf(yv.x, wl[j].x, z);
            z = fmaf(yv.y, wl[j].y, z);
            z = fmaf(yv.z, wl[j].z, z);
            z = fmaf(yv.w, wl[j].w, z);
        }
        __syncwarp();
        out[v * C + lane] = z;
    }
}

extern "C" void kernel_launch(void* const* d_in, const int* in_sizes, int n_in,
                              void* d_out, int out_size)
{
    const float* x     = (const float*)d_in[0];
    const int*   nbr   = (const int*)d_in[1];
    const float* Wc    = (const float*)d_in[2];
    const float* bc    = (const float*)d_in[3];
    const float* gamma = (const float*)d_in[4];
    const float* beta  = (const float*)d_in[5];
    const float* Wl    = (const float*)d_in[6];
    const float* bl    = (const float*)d_in[7];
    float* out = (float*)d_out;

    int n  = in_sizes[0] / C;          // voxels
    int kt = in_sizes[1] / n;          // taps (125)
    int wtot = in_sizes[2];            // K*CIN*COUT

    transpose_w<<<(wtot + 255) / 256, 256>>>(Wc, wtot);
    conv_kernel<<<(n + VB - 1) / VB, 256>>>(x, nbr, bc, out, n, kt);
    bn_partial<<<512, 256>>>(out, n);
    bn_final<<<1, 256>>>(n, 512);
    apply_kernel<<<1024, 256>>>(gamma, beta, Wl, bl, out, n);
}

// round 2
// speedup vs baseline: 1.0007x; 1.0007x over previous
#include <cuda_runtime.h>

#define C 32
#define KT_MAX 125
#define EPSBN 1e-5f

// ---- device scratch (no allocations allowed) ----
__device__ __align__(16) float g_Wt[KT_MAX * C * C];   // [K][COUT][CIN]
__device__ float g_part[512 * 2 * C];                  // per-block partial sums / sumsq
__device__ float g_mean[C];
__device__ float g_rstd[C];

// ---------------- W transpose: [K][CIN][COUT] -> [K][COUT][CIN] ----------------
__global__ void transpose_w(const float* __restrict__ W, int total) {
    int i = blockIdx.x * blockDim.x + threadIdx.x;
    if (i < total) {
        int k = i / (C * C);
        int r = i % (C * C);
        int cin = r / C, cout = r % C;
        g_Wt[k * C * C + cout * C + cin] = W[i];
    }
}

// ---------------- sparse conv ----------------
#define VW 16                 // voxels per warp
#define WARPS 8
#define VB (VW * WARPS)       // voxels per block

__global__ __launch_bounds__(256) void conv_kernel(
    const float* __restrict__ x, const int* __restrict__ nbr,
    const float* __restrict__ bconv, float* __restrict__ out,
    int n, int kt)
{
    __shared__ __align__(16) float xsm[WARPS][VW][C];
    int warp = threadIdx.x >> 5, lane = threadIdx.x & 31;
    int v0 = blockIdx.x * VB + warp * VW;

    float b = bconv[lane];
    float acc[VW];
#pragma unroll
    for (int i = 0; i < VW; i++) acc[i] = b;

    for (int k = 0; k < kt; k++) {
        // per-lane weight column for this tap: Wt[k][lane][0..31], coalesced 128B/lane
        float4 w[8];
        const float4* wp = (const float4*)(g_Wt + k * C * C + lane * C);
#pragma unroll
        for (int j = 0; j < 8; j++) w[j] = wp[j];

        // stage valid gathered rows into smem (warp-uniform validity)
        unsigned vm = 0;
#pragma unroll
        for (int i = 0; i < VW; i++) {
            int v = v0 + i;
            if (v < n) {
                int idx = __ldg(&nbr[(long long)v * kt + k]);
                if (idx >= 0) {
                    vm |= (1u << i);
                    xsm[warp][i][lane] = x[idx * C + lane];
                }
            }
        }
        __syncwarp();

        // compute: per valid voxel 8x LDS.128 broadcast + 32 FFMA
#pragma unroll
        for (int i = 0; i < VW; i++) {
            if ((vm >> i) & 1u) {
                const float4* xs = (const float4*)xsm[warp][i];
                float a = acc[i];
#pragma unroll
                for (int j = 0; j < 8; j++) {
                    float4 xv = xs[j];
                    a = fmaf(xv.x, w[j].x, a);
                    a = fmaf(xv.y, w[j].y, a);
                    a = fmaf(xv.z, w[j].z, a);
                    a = fmaf(xv.w, w[j].w, a);
                }
                acc[i] = a;
            }
        }
        __syncwarp();
    }

#pragma unroll
    for (int i = 0; i < VW; i++) {
        int v = v0 + i;
        if (v < n) out[v * C + lane] = acc[i];
    }
}

// ---------------- BN stats: stage 1 (deterministic partials) ----------------
__global__ __launch_bounds__(256) void bn_partial(const float* __restrict__ out, int n) {
    int lane = threadIdx.x & 31, w = threadIdx.x >> 5;
    float s = 0.f, s2 = 0.f;
    for (int r = blockIdx.x * 8 + w; r < n; r += gridDim.x * 8) {
        float v = out[r * C + lane];
        s += v;
        s2 += v * v;
    }
    __shared__ float sh[2][8][C];
    sh[0][w][lane] = s;
    sh[1][w][lane] = s2;
    __syncthreads();
    if (threadIdx.x < C) {
        float S = 0.f, S2 = 0.f;
#pragma unroll
        for (int j = 0; j < 8; j++) { S += sh[0][j][threadIdx.x]; S2 += sh[1][j][threadIdx.x]; }
        g_part[blockIdx.x * 2 * C + threadIdx.x] = S;
        g_part[blockIdx.x * 2 * C + C + threadIdx.x] = S2;
    }
}

// ---------------- BN stats: stage 2 ----------------
__global__ void bn_final(int n, int nblocks) {
    int lane = threadIdx.x & 31, w = threadIdx.x >> 5;   // 256 threads, 8 warps
    float S = 0.f, S2 = 0.f;
    for (int b = w; b < nblocks; b += 8) {
        S  += g_part[b * 2 * C + lane];
        S2 += g_part[b * 2 * C + C + lane];
    }
    __shared__ float sh[2][8][C];
    sh[0][w][lane] = S;
    sh[1][w][lane] = S2;
    __syncthreads();
    if (threadIdx.x < C) {
        float a = 0.f, a2 = 0.f;
#pragma unroll
        for (int j = 0; j < 8; j++) { a += sh[0][j][threadIdx.x]; a2 += sh[1][j][threadIdx.x]; }
        float mean = a / (float)n;
        float var = a2 / (float)n - mean * mean;
        g_mean[threadIdx.x] = mean;
        g_rstd[threadIdx.x] = rsqrtf(var + EPSBN);
    }
}

// ---------------- BN apply + ELU + linear (in-place on out) ----------------
__global__ __launch_bounds__(256) void apply_kernel(
    const float* __restrict__ gamma, const float* __restrict__ beta,
    const float* __restrict__ Wlin, const float* __restrict__ blin,
    float* __restrict__ out, int n)
{
    __shared__ __align__(16) float ysm[WARPS][C];
    int lane = threadIdx.x & 31, w = threadIdx.x >> 5;
    float m = g_mean[lane], rs = g_rstd[lane];
    float ga = gamma[lane], be = beta[lane], bl = blin[lane];
    // z[o] = sum_c y[c] * Wlin[o][c] + bl[o]; per-lane row is contiguous
    float4 wl[8];
    const float4* wp = (const float4*)(Wlin + lane * C);
#pragma unroll
    for (int j = 0; j < 8; j++) wl[j] = wp[j];

    for (int v = blockIdx.x * 8 + w; v < n; v += gridDim.x * 8) {
        float o = out[v * C + lane];
        float y = fmaf((o - m) * rs, ga, be);
        y = (y > 0.f) ? y : expm1f(y);
        ysm[w][lane] = y;
        __syncwarp();
        const float4* ys = (const float4*)ysm[w];
        float z = bl;
#pragma unroll
        for (int j = 0; j < 8; j++) {
            float4 yv = ys[j];
            z = fmaf(yv.x, wl[j].x, z);
            z = fmaf(yv.y, wl[j].y, z);
            z = fmaf(yv.z, wl[j].z, z);
            z = fmaf(yv.w, wl[j].w, z);
        }
        __syncwarp();
        out[v * C + lane] = z;
    }
}

extern "C" void kernel_launch(void* const* d_in, const int* in_sizes, int n_in,
                              void* d_out, int out_size)
{
    const float* x     = (const float*)d_in[0];
    const int*   nbr   = (const int*)d_in[1];
    const float* Wc    = (const float*)d_in[2];
    const float* bc    = (const float*)d_in[3];
    const float* gamma = (const float*)d_in[4];
    const float* beta  = (const float*)d_in[5];
    const float* Wl    = (const float*)d_in[6];
    const float* bl    = (const float*)d_in[7];
    float* out = (float*)d_out;

    int n  = in_sizes[0] / C;          // voxels
    int kt = in_sizes[1] / n;          // taps (125)
    int wtot = in_sizes[2];            // K*CIN*COUT

    transpose_w<<<(wtot + 255) / 256, 256>>>(Wc, wtot);
    conv_kernel<<<(n + VB - 1) / VB, 256>>>(x, nbr, bc, out, n, kt);
    bn_partial<<<512, 256>>>(out, n);
    bn_final<<<1, 256>>>(n, 512);
    apply_kernel<<<1024, 256>>>(gamma, beta, Wl, bl, out, n);
}

// round 3
// speedup vs baseline: 1.5264x; 1.5253x over previous
#include <cuda_runtime.h>
#include <cstdint>

#define C 32
#define EPSBN 1e-5f

// conv tile config
#define CWARPS 4
#define VW 16
#define VB (CWARPS * VW)
#define NSTG 4            // smem stage ring (power of 2)
#define GLA 3             // gather lookahead (cp.async groups in flight)
#define MAXBLK 8192

// ---- device scratch (no allocations allowed) ----
__device__ __align__(16) float g_Wt[125 * C * C];     // [K][COUT][CIN]
__device__ float g_part[MAXBLK * 2 * C];              // per-block partial sums / sumsq
__device__ float g_mean[C];
__device__ float g_rstd[C];

// ---- cp.async helpers ----
__device__ __forceinline__ void cp_async16(uint32_t dst, const void* src) {
    asm volatile("cp.async.cg.shared.global [%0], [%1], 16;" :: "r"(dst), "l"(src));
}
__device__ __forceinline__ void cp_commit() { asm volatile("cp.async.commit_group;"); }
template <int N> __device__ __forceinline__ void cp_wait() {
    asm volatile("cp.async.wait_group %0;" :: "n"(N));
}

// ---------------- W transpose: [K][CIN][COUT] -> [K][COUT][CIN] ----------------
__global__ void transpose_w(const float* __restrict__ W, int total) {
    int i = blockIdx.x * blockDim.x + threadIdx.x;
    if (i < total) {
        int k = i / (C * C);
        int r = i % (C * C);
        int cin = r / C, cout = r % C;
        g_Wt[k * C * C + cout * C + cin] = W[i];
    }
}

// ---------------- pipelined sparse conv (KT compile-time) ----------------
template <int KT>
__global__ __launch_bounds__(128, 4) void conv_pipe(
    const float* __restrict__ x, const int* __restrict__ nbr,
    const float* __restrict__ bconv, float* __restrict__ out, int n)
{
    __shared__ __align__(16) float xst[CWARPS][NSTG][VW][C];
    __shared__ float red[2][CWARPS][C];

    const int warp = threadIdx.x >> 5, lane = threadIdx.x & 31;
    const int v0 = blockIdx.x * VB + warp * VW;
    const int bi = lane >> 3;     // this lane's base voxel (bi + 4m, m=0..3)
    const int cj = lane & 7;      // 16B chunk within the 128B row
    const uint32_t stbase = (uint32_t)__cvta_generic_to_shared(&xst[warp][0][0][0]);

    // precomputed per-lane nbr row pointers + bounds flags
    const int* np[4];
    bool vok[4];
#pragma unroll
    for (int m = 0; m < 4; m++) {
        int v = v0 + bi + 4 * m;
        vok[m] = (v < n);
        np[m] = nbr + (size_t)(vok[m] ? v : 0) * KT;
    }

    float b = bconv[lane];
    float acc[VW];
#pragma unroll
    for (int i = 0; i < VW; i++) acc[i] = b;

    int nidx[NSTG][4];            // nbr-index register ring
    unsigned vmask[NSTG];         // per-stage warp-wide validity mask

    // --- pipeline stage helpers ---
    auto FETCH = [&](int tt) {    // prefetch nbr indices for tap tt
        int s = tt & (NSTG - 1);
#pragma unroll
        for (int m = 0; m < 4; m++)
            nidx[s][m] = vok[m] ? __ldg(np[m] + tt) : -1;
    };
    auto ISSUE = [&](int tt) {    // issue cp.async gathers for tap tt
        int s = tt & (NSTG - 1);
        unsigned bits = 0;
#pragma unroll
        for (int m = 0; m < 4; m++) {
            int id = nidx[s][m];
            int i = bi + 4 * m;
            if (id >= 0) {
                bits |= 1u << i;
                cp_async16(stbase + (uint32_t)(((s * VW + i) * C + cj * 4) * 4),
                           x + (size_t)id * C + cj * 4);
            }
        }
        vmask[s] = __reduce_or_sync(0xffffffffu, bits);
    };
    auto COMPUTE = [&](int tt) {
        int s = tt & (NSTG - 1);
        unsigned vm = vmask[s];
        const float4* wp = (const float4*)(g_Wt + tt * (C * C) + lane * C);
        float4 w[8];
#pragma unroll
        for (int j = 0; j < 8; j++) w[j] = wp[j];
#pragma unroll
        for (int i = 0; i < VW; i++) {
            if ((vm >> i) & 1u) {
                const float4* xs = (const float4*)&xst[warp][s][i][0];
                float a = acc[i];
#pragma unroll
                for (int j = 0; j < 8; j++) {
                    float4 xv = xs[j];
                    a = fmaf(xv.x, w[j].x, a);
                    a = fmaf(xv.y, w[j].y, a);
                    a = fmaf(xv.z, w[j].z, a);
                    a = fmaf(xv.w, w[j].w, a);
                }
                acc[i] = a;
            }
        }
    };

    // --- prologue: fill the pipeline (3 committed groups, 6 prefetched taps) ---
    FETCH(0);
    if (KT > 1) FETCH(1);
    if (KT > 2) FETCH(2);
    if (KT > 3) FETCH(3);
    ISSUE(0); cp_commit();
    if (KT > 4) FETCH(4);
    if (KT > 1) ISSUE(1);
    cp_commit();
    if (KT > 5) FETCH(5);
    if (KT > 2) ISSUE(2);
    cp_commit();

    // --- main loop ---
#pragma unroll 4
    for (int t = 0; t < KT; t++) {
        if (t + 6 < KT) FETCH(t + 6);
        if (t + GLA < KT) ISSUE(t + GLA);
        cp_commit();
        cp_wait<GLA>();
        __syncwarp();
        COMPUTE(t);
    }

    // --- epilogue: store out + fused BN stage-1 partials ---
    float s1 = 0.f, s2 = 0.f;
#pragma unroll
    for (int i = 0; i < VW; i++) {
        int v = v0 + i;
        if (v < n) {
            float a = acc[i];
            out[(size_t)v * C + lane] = a;
            s1 += a;
            s2 += a * a;
        }
    }
    red[0][warp][lane] = s1;
    red[1][warp][lane] = s2;
    __syncthreads();
    if (threadIdx.x < C) {
        float a = 0.f, b2 = 0.f;
#pragma unroll
        for (int w = 0; w < CWARPS; w++) { a += red[0][w][threadIdx.x]; b2 += red[1][w][threadIdx.x]; }
        g_part[blockIdx.x * 2 * C + threadIdx.x] = a;
        g_part[blockIdx.x * 2 * C + C + threadIdx.x] = b2;
    }
}

// ---------------- generic fallback conv (non-pipelined, writes out only) ----------------
__global__ __launch_bounds__(256) void conv_generic(
    const float* __restrict__ x, const int* __restrict__ nbr,
    const float* __restrict__ bconv, float* __restrict__ out,
    int n, int kt)
{
    __shared__ __align__(16) float xsm[8][VW][C];
    int warp = threadIdx.x >> 5, lane = threadIdx.x & 31;
    int v0 = blockIdx.x * (VW * 8) + warp * VW;
    float b = bconv[lane];
    float acc[VW];
#pragma unroll
    for (int i = 0; i < VW; i++) acc[i] = b;
    for (int k = 0; k < kt; k++) {
        float4 w[8];
        const float4* wp = (const float4*)(g_Wt + k * C * C + lane * C);
#pragma unroll
        for (int j = 0; j < 8; j++) w[j] = wp[j];
        unsigned vm = 0;
#pragma unroll
        for (int i = 0; i < VW; i++) {
            int v = v0 + i;
            if (v < n) {
                int idx = __ldg(&nbr[(size_t)v * kt + k]);
                if (idx >= 0) { vm |= (1u << i); xsm[warp][i][lane] = x[(size_t)idx * C + lane]; }
            }
        }
        __syncwarp();
#pragma unroll
        for (int i = 0; i < VW; i++) {
            if ((vm >> i) & 1u) {
                const float4* xs = (const float4*)xsm[warp][i];
                float a = acc[i];
#pragma unroll
                for (int j = 0; j < 8; j++) {
                    float4 xv = xs[j];
                    a = fmaf(xv.x, w[j].x, a); a = fmaf(xv.y, w[j].y, a);
                    a = fmaf(xv.z, w[j].z, a); a = fmaf(xv.w, w[j].w, a);
                }
                acc[i] = a;
            }
        }
        __syncwarp();
    }
#pragma unroll
    for (int i = 0; i < VW; i++) {
        int v = v0 + i;
        if (v < n) out[(size_t)v * C + lane] = acc[i];
    }
}

// fallback BN stage-1 (only used on generic path)
__global__ __launch_bounds__(256) void bn_partial(const float* __restrict__ out, int n) {
    int lane = threadIdx.x & 31, w = threadIdx.x >> 5;
    float s = 0.f, s2 = 0.f;
    for (int r = blockIdx.x * 8 + w; r < n; r += gridDim.x * 8) {
        float v = out[(size_t)r * C + lane];
        s += v; s2 += v * v;
    }
    __shared__ float sh[2][8][C];
    sh[0][w][lane] = s; sh[1][w][lane] = s2;
    __syncthreads();
    if (threadIdx.x < C) {
        float S = 0.f, S2 = 0.f;
#pragma unroll
        for (int j = 0; j < 8; j++) { S += sh[0][j][threadIdx.x]; S2 += sh[1][j][threadIdx.x]; }
        g_part[blockIdx.x * 2 * C + threadIdx.x] = S;
        g_part[blockIdx.x * 2 * C + C + threadIdx.x] = S2;
    }
}

// ---------------- BN stats: final reduce ----------------
__global__ void bn_final(int n, int nblocks) {
    int lane = threadIdx.x & 31, w = threadIdx.x >> 5;   // 256 threads, 8 warps
    float S = 0.f, S2 = 0.f;
    for (int b = w; b < nblocks; b += 8) {
        S  += g_part[b * 2 * C + lane];
        S2 += g_part[b * 2 * C + C + lane];
    }
    __shared__ float sh[2][8][C];
    sh[0][w][lane] = S; sh[1][w][lane] = S2;
    __syncthreads();
    if (threadIdx.x < C) {
        float a = 0.f, a2 = 0.f;
#pragma unroll
        for (int j = 0; j < 8; j++) { a += sh[0][j][threadIdx.x]; a2 += sh[1][j][threadIdx.x]; }
        float mean = a / (float)n;
        float var = a2 / (float)n - mean * mean;
        g_mean[threadIdx.x] = mean;
        g_rstd[threadIdx.x] = rsqrtf(var + EPSBN);
    }
}

// ---------------- BN apply + ELU + linear (in-place on out) ----------------
__global__ __launch_bounds__(256) void apply_kernel(
    const float* __restrict__ gamma, const float* __restrict__ beta,
    const float* __restrict__ Wlin, const float* __restrict__ blin,
    float* __restrict__ out, int n)
{
    __shared__ __align__(16) float ysm[8][C];
    int lane = threadIdx.x & 31, w = threadIdx.x >> 5;
    float m = g_mean[lane], rs = g_rstd[lane];
    float ga = gamma[lane], be = beta[lane], bl = blin[lane];
    float4 wl[8];
    const float4* wp = (const float4*)(Wlin + lane * C);
#pragma unroll
    for (int j = 0; j < 8; j++) wl[j] = wp[j];

    for (int v = blockIdx.x * 8 + w; v < n; v += gridDim.x * 8) {
        float o = out[(size_t)v * C + lane];
        float y = fmaf((o - m) * rs, ga, be);
        y = (y > 0.f) ? y : expm1f(y);
        ysm[w][lane] = y;
        __syncwarp();
        const float4* ys = (const float4*)ysm[w];
        float z = bl;
#pragma unroll
        for (int j = 0; j < 8; j++) {
            float4 yv = ys[j];
            z = fmaf(yv.x, wl[j].x, z); z = fmaf(yv.y, wl[j].y, z);
            z = fmaf(yv.z, wl[j].z, z); z = fmaf(yv.w, wl[j].w, z);
        }
        __syncwarp();
        out[(size_t)v * C + lane] = z;
    }
}

extern "C" void kernel_launch(void* const* d_in, const int* in_sizes, int n_in,
                              void* d_out, int out_size)
{
    const float* x     = (const float*)d_in[0];
    const int*   nbr   = (const int*)d_in[1];
    const float* Wc    = (const float*)d_in[2];
    const float* bc    = (const float*)d_in[3];
    const float* gamma = (const float*)d_in[4];
    const float* beta  = (const float*)d_in[5];
    const float* Wl    = (const float*)d_in[6];
    const float* bl    = (const float*)d_in[7];
    float* out = (float*)d_out;

    int n  = in_sizes[0] / C;          // voxels
    int kt = in_sizes[1] / n;          // taps
    int wtot = in_sizes[2];            // K*CIN*COUT

    transpose_w<<<(wtot + 255) / 256, 256>>>(Wc, wtot);

    int nb = (n + VB - 1) / VB;
    if (kt == 125 && nb <= MAXBLK) {
        conv_pipe<125><<<nb, 128>>>(x, nbr, bc, out, n);
        bn_final<<<1, 256>>>(n, nb);
    } else {
        conv_generic<<<(n + VW * 8 - 1) / (VW * 8), 256>>>(x, nbr, bc, out, n, kt);
        bn_partial<<<512, 256>>>(out, n);
        bn_final<<<1, 256>>>(n, 512);
    }
    apply_kernel<<<1024, 256>>>(gamma, beta, Wl, bl, out, n);
}

// round 5
// speedup vs baseline: 2.5504x; 1.6708x over previous
#include <cuda_runtime.h>
#include <cstdint>

#define C 32
#define EPSBN 1e-5f

#define CWARPS 8
#define VW 8
#define VB (CWARPS * VW)      // 64 voxels / block
#define NSTG 4                // stage ring
#define MAXBLK 8192
#define MAXN 500000
#define KTAP 125

typedef unsigned long long ull;

// ---- device scratch (no allocations allowed) ----
__device__ __align__(16) float g_Wt[KTAP * C * C];    // [K][COUT][CIN]
__device__ int   g_nbrT[(size_t)KTAP * MAXN];         // [K][N] transposed indices
__device__ float g_part[MAXBLK * 2 * C];
__device__ float g_mean[C];
__device__ float g_rstd[C];

// ---- helpers ----
__device__ __forceinline__ void cp_async16(uint32_t dst, const void* src) {
    asm volatile("cp.async.cg.shared.global [%0], [%1], 16;" :: "r"(dst), "l"(src));
}
__device__ __forceinline__ void cp_commit() { asm volatile("cp.async.commit_group;"); }
template <int N_> __device__ __forceinline__ void cp_wait() {
    asm volatile("cp.async.wait_group %0;" :: "n"(N_));
}
__device__ __forceinline__ ull fma2(ull a, ull b, ull c) {
    ull d;
    asm("fma.rn.f32x2 %0, %1, %2, %3;" : "=l"(d) : "l"(a), "l"(b), "l"(c));
    return d;
}
union F2U { float2 f; ull u; };

// ---------------- W transpose: [K][CIN][COUT] -> [K][COUT][CIN] ----------------
__global__ void transpose_w(const float* __restrict__ W, int total) {
    int i = blockIdx.x * blockDim.x + threadIdx.x;
    if (i < total) {
        int k = i / (C * C);
        int r = i % (C * C);
        int cin = r / C, cout = r % C;
        g_Wt[k * C * C + cout * C + cin] = W[i];
    }
}

// ---------------- nbr transpose: [N][K] -> [K][N] (tiled, coalesced) ----------------
__global__ void transpose_nbr(const int* __restrict__ nbr, int n, int kt) {
    __shared__ int t[32][33];
    int k0 = blockIdx.y * 32, vb = blockIdx.x * 32;
    int kk = k0 + threadIdx.x;
#pragma unroll
    for (int dy = 0; dy < 32; dy += 8) {
        int v = vb + threadIdx.y + dy;
        if (v < n && kk < kt) t[threadIdx.y + dy][threadIdx.x] = nbr[(size_t)v * kt + kk];
    }
    __syncthreads();
    int vw = vb + threadIdx.x;
#pragma unroll
    for (int dy = 0; dy < 32; dy += 8) {
        int k = k0 + threadIdx.y + dy;
        if (k < kt && vw < n) g_nbrT[(size_t)k * n + vw] = t[threadIdx.x][threadIdx.y + dy];
    }
}

// smem index macros (float offsets)
#define XSTOFF(w_, s_, i_) (((((w_) * NSTG + (s_)) * VW) + (i_)) * C)
#define WSTOFF(s_, r_, c_) ((s_) * C * C + (r_) * C + ((((c_) ^ ((r_) & 7))) << 2))

// ---------------- pipelined sparse conv ----------------
template <int KT>
__global__ __launch_bounds__(256, 3) void conv_pipe(
    const float* __restrict__ x, const float* __restrict__ bconv,
    float* __restrict__ out, int n)
{
    __shared__ __align__(16) float smem[CWARPS * NSTG * VW * C + NSTG * C * C]; // 48KB
    float* xst = smem;
    float* wst = smem + CWARPS * NSTG * VW * C;

    const int tid = threadIdx.x;
    const int warp = tid >> 5, lane = tid & 31;
    const int bi = lane >> 3, cj = lane & 7;
    const int v0 = blockIdx.x * VB + warp * VW;
    const uint32_t xbase = (uint32_t)__cvta_generic_to_shared(xst);
    const uint32_t wbase = (uint32_t)__cvta_generic_to_shared(wst);

    int vv[2]; bool vok[2];
#pragma unroll
    for (int m = 0; m < 2; m++) { vv[m] = v0 + bi + 4 * m; vok[m] = (vv[m] < n); }

    F2U pk; pk.f = make_float2(bconv[lane], 0.f);
    ull acc2[VW];
#pragma unroll
    for (int i = 0; i < VW; i++) acc2[i] = pk.u;

    int nidx[NSTG][2];
    unsigned vmask[NSTG];

    auto FETCH = [&](int tt) {
        int s = tt & (NSTG - 1);
#pragma unroll
        for (int m = 0; m < 2; m++)
            nidx[s][m] = vok[m] ? __ldg(&g_nbrT[(size_t)tt * n + vv[m]]) : -1;
    };
    auto ISSUE = [&](int tt) {
        int s = tt & (NSTG - 1);
        unsigned bits = 0;
#pragma unroll
        for (int m = 0; m < 2; m++) {
            int id = nidx[s][m];
            int i = bi + 4 * m;
            if (id >= 0) {
                bits |= 1u << i;
                cp_async16(xbase + (uint32_t)((XSTOFF(warp, s, i) + cj * 4) * 4),
                           x + (size_t)id * C + cj * 4);
            }
        }
        vmask[s] = __reduce_or_sync(0xffffffffu, bits);
        // stage this tap's 4KB weight tile: each of 256 threads copies one 16B chunk
        cp_async16(wbase + (uint32_t)(WSTOFF(s, tid >> 3, tid & 7) * 4),
                   g_Wt + tt * (C * C) + tid * 4);
    };
    auto COMPUTE = [&](int tt) {
        int s = tt & (NSTG - 1);
        unsigned vm = vmask[s];
#pragma unroll
        for (int i = 0; i < VW; i++) {
            if ((vm >> i) & 1u) {
                ull a = acc2[i];
#pragma unroll
                for (int j = 0; j < 8; j++) {
                    ulonglong2 w2 = *(const ulonglong2*)(wst + WSTOFF(s, lane, j));
                    ulonglong2 x2 = *(const ulonglong2*)(xst + XSTOFF(warp, s, i) + j * 4);
                    a = fma2(x2.x, w2.x, a);
                    a = fma2(x2.y, w2.y, a);
                }
                acc2[i] = a;
            }
        }
    };

    // prologue: interleaved so FETCH(t+4) never clobbers a slot before ISSUE(t) reads it
    FETCH(0); FETCH(1); FETCH(2); FETCH(3);
    ISSUE(0); cp_commit();
    FETCH(4);                    // slot 0: tap 0 already issued
    ISSUE(1); cp_commit();
    FETCH(5);                    // slot 1: tap 1 already issued
    ISSUE(2); cp_commit();

#pragma unroll 4
    for (int t = 0; t < KT; t++) {
        if (t + 6 < KT) FETCH(t + 6);   // slot (t+2)&3: tap t+2 issued at iter t-1/prologue
        cp_wait<2>();            // tap t's gathers + weights (all threads) landed
        __syncthreads();         // weights staged by all threads now visible
        COMPUTE(t);
        if (t + 3 < KT) ISSUE(t + 3);   // writes stage (t-1)&3: all readers passed barrier
        cp_commit();
    }

    // epilogue: store out + fused BN partials (reuse own warp's xst region)
    float s1 = 0.f, s2 = 0.f;
#pragma unroll
    for (int i = 0; i < VW; i++) {
        int v = v0 + i;
        if (v < n) {
            F2U u; u.u = acc2[i];
            float a = u.f.x + u.f.y;
            out[(size_t)v * C + lane] = a;
            s1 += a;
            s2 += a * a;
        }
    }
    xst[warp * (NSTG * VW * C) + lane] = s1;
    xst[warp * (NSTG * VW * C) + C + lane] = s2;
    __syncthreads();
    if (tid < C) {
        float a = 0.f, b2 = 0.f;
#pragma unroll
        for (int w = 0; w < CWARPS; w++) {
            a  += xst[w * (NSTG * VW * C) + tid];
            b2 += xst[w * (NSTG * VW * C) + C + tid];
        }
        g_part[blockIdx.x * 2 * C + tid] = a;
        g_part[blockIdx.x * 2 * C + C + tid] = b2;
    }
}

// ---------------- generic fallback conv ----------------
__global__ __launch_bounds__(256) void conv_generic(
    const float* __restrict__ x, const int* __restrict__ nbr,
    const float* __restrict__ bconv, float* __restrict__ out,
    int n, int kt)
{
    __shared__ __align__(16) float xsm[8][16][C];
    int warp = threadIdx.x >> 5, lane = threadIdx.x & 31;
    int v0 = blockIdx.x * 128 + warp * 16;
    float b = bconv[lane];
    float acc[16];
#pragma unroll
    for (int i = 0; i < 16; i++) acc[i] = b;
    for (int k = 0; k < kt; k++) {
        float4 w[8];
        const float4* wp = (const float4*)(g_Wt + k * C * C + lane * C);
#pragma unroll
        for (int j = 0; j < 8; j++) w[j] = wp[j];
        unsigned vm = 0;
#pragma unroll
        for (int i = 0; i < 16; i++) {
            int v = v0 + i;
            if (v < n) {
                int idx = __ldg(&nbr[(size_t)v * kt + k]);
                if (idx >= 0) { vm |= (1u << i); xsm[warp][i][lane] = x[(size_t)idx * C + lane]; }
            }
        }
        __syncwarp();
#pragma unroll
        for (int i = 0; i < 16; i++) {
            if ((vm >> i) & 1u) {
                const float4* xs = (const float4*)xsm[warp][i];
                float a = acc[i];
#pragma unroll
                for (int j = 0; j < 8; j++) {
                    float4 xv = xs[j];
                    a = fmaf(xv.x, w[j].x, a); a = fmaf(xv.y, w[j].y, a);
                    a = fmaf(xv.z, w[j].z, a); a = fmaf(xv.w, w[j].w, a);
                }
                acc[i] = a;
            }
        }
        __syncwarp();
    }
#pragma unroll
    for (int i = 0; i < 16; i++) {
        int v = v0 + i;
        if (v < n) out[(size_t)v * C + lane] = acc[i];
    }
}

__global__ __launch_bounds__(256) void bn_partial(const float* __restrict__ out, int n) {
    int lane = threadIdx.x & 31, w = threadIdx.x >> 5;
    float s = 0.f, s2 = 0.f;
    for (int r = blockIdx.x * 8 + w; r < n; r += gridDim.x * 8) {
        float v = out[(size_t)r * C + lane];
        s += v; s2 += v * v;
    }
    __shared__ float sh[2][8][C];
    sh[0][w][lane] = s; sh[1][w][lane] = s2;
    __syncthreads();
    if (threadIdx.x < C) {
        float S = 0.f, S2 = 0.f;
#pragma unroll
        for (int j = 0; j < 8; j++) { S += sh[0][j][threadIdx.x]; S2 += sh[1][j][threadIdx.x]; }
        g_part[blockIdx.x * 2 * C + threadIdx.x] = S;
        g_part[blockIdx.x * 2 * C + C + threadIdx.x] = S2;
    }
}

// ---------------- BN final reduce (1024 threads) ----------------
__global__ void bn_final(int n, int nblocks) {
    int lane = threadIdx.x & 31, w = threadIdx.x >> 5;   // 32 warps
    float S = 0.f, S2 = 0.f;
    for (int b = w; b < nblocks; b += 32) {
        S  += g_part[b * 2 * C + lane];
        S2 += g_part[b * 2 * C + C + lane];
    }
    __shared__ float sh[2][32][C];
    sh[0][w][lane] = S; sh[1][w][lane] = S2;
    __syncthreads();
    if (threadIdx.x < C) {
        float a = 0.f, a2 = 0.f;
#pragma unroll
        for (int j = 0; j < 32; j++) { a += sh[0][j][threadIdx.x]; a2 += sh[1][j][threadIdx.x]; }
        float mean = a / (float)n;
        float var = a2 / (float)n - mean * mean;
        g_mean[threadIdx.x] = mean;
        g_rstd[threadIdx.x] = rsqrtf(var + EPSBN);
    }
}

// ---------------- BN apply + ELU + linear (4 voxels/warp-iter, f32x2) ----------------
__global__ __launch_bounds__(256) void apply_kernel(
    const float* __restrict__ gamma, const float* __restrict__ beta,
    const float* __restrict__ Wlin, const float* __restrict__ blin,
    float* __restrict__ out, int n)
{
    __shared__ __align__(16) float ysm[8][4][C];
    int lane = threadIdx.x & 31, w = threadIdx.x >> 5;
    float m = g_mean[lane], rs = g_rstd[lane];
    float ga = gamma[lane], be = beta[lane];
    F2U blu; blu.f = make_float2(blin[lane], 0.f);

    ull wl[16];
    const ull* wp = (const ull*)(Wlin + lane * C);
#pragma unroll
    for (int p = 0; p < 16; p++) wl[p] = wp[p];

    for (int v4 = (blockIdx.x * 8 + w) * 4; v4 < n; v4 += gridDim.x * 32) {
        float y[4];
#pragma unroll
        for (int q = 0; q < 4; q++) {
            int v = v4 + q;
            float o = (v < n) ? out[(size_t)v * C + lane] : 0.f;
            float t = fmaf((o - m) * rs, ga, be);
            y[q] = (t > 0.f) ? t : expm1f(t);
            ysm[w][q][lane] = y[q];
        }
        __syncwarp();
#pragma unroll
        for (int q = 0; q < 4; q++) {
            int v = v4 + q;
            if (v < n) {
                const ull* ys = (const ull*)ysm[w][q];
                ull z2 = blu.u;
#pragma unroll
                for (int p = 0; p < 16; p++) z2 = fma2(ys[p], wl[p], z2);
                F2U r; r.u = z2;
                out[(size_t)v * C + lane] = r.f.x + r.f.y;
            }
        }
        __syncwarp();
    }
}

extern "C" void kernel_launch(void* const* d_in, const int* in_sizes, int n_in,
                              void* d_out, int out_size)
{
    const float* x     = (const float*)d_in[0];
    const int*   nbr   = (const int*)d_in[1];
    const float* Wc    = (const float*)d_in[2];
    const float* bc    = (const float*)d_in[3];
    const float* gamma = (const float*)d_in[4];
    const float* beta  = (const float*)d_in[5];
    const float* Wl    = (const float*)d_in[6];
    const float* bl    = (const float*)d_in[7];
    float* out = (float*)d_out;

    int n  = in_sizes[0] / C;
    int kt = in_sizes[1] / n;
    int wtot = in_sizes[2];

    transpose_w<<<(wtot + 255) / 256, 256>>>(Wc, wtot);

    int nb = (n + VB - 1) / VB;
    if (kt == KTAP && n <= MAXN && nb <= MAXBLK) {
        dim3 tg((n + 31) / 32, (kt + 31) / 32);
        transpose_nbr<<<tg, dim3(32, 8)>>>(nbr, n, kt);
        conv_pipe<KTAP><<<nb, 256>>>(x, bc, out, n);
        bn_final<<<1, 1024>>>(n, nb);
    } else {
        conv_generic<<<(n + 127) / 128, 256>>>(x, nbr, bc, out, n, kt);
        bn_partial<<<512, 256>>>(out, n);
        bn_final<<<1, 1024>>>(n, 512);
    }
    apply_kernel<<<2048, 256>>>(gamma, beta, Wl, bl, out, n);
}

// round 6
// speedup vs baseline: 2.5504x; 1.0000x over previous
#include <cuda_runtime.h>
#include <cstdint>

#define C 32
#define EPSBN 1e-5f

#define CWARPS 8
#define VW 8
#define VB (CWARPS * VW)      // 64 voxels / block
#define NSTG 4                // stage ring
#define MAXBLK 8192
#define MAXN 500000
#define KTAP 125

typedef unsigned long long ull;

// ---- device scratch (no allocations allowed) ----
__device__ __align__(16) float g_Wt[KTAP * C * C];    // [K][COUT][CIN]
__device__ int   g_nbrT[(size_t)KTAP * MAXN];         // [K][N] transposed indices
__device__ float g_part[MAXBLK * 2 * C];
__device__ float g_mean[C];
__device__ float g_rstd[C];

// ---- helpers ----
__device__ __forceinline__ void cp_async16(uint32_t dst, const void* src) {
    asm volatile("cp.async.cg.shared.global [%0], [%1], 16;" :: "r"(dst), "l"(src));
}
__device__ __forceinline__ void cp_commit() { asm volatile("cp.async.commit_group;"); }
template <int N_> __device__ __forceinline__ void cp_wait() {
    asm volatile("cp.async.wait_group %0;" :: "n"(N_));
}
__device__ __forceinline__ ull fma2(ull a, ull b, ull c) {
    ull d;
    asm("fma.rn.f32x2 %0, %1, %2, %3;" : "=l"(d) : "l"(a), "l"(b), "l"(c));
    return d;
}
union F2U { float2 f; ull u; };

// ---------------- W transpose: [K][CIN][COUT] -> [K][COUT][CIN] ----------------
__global__ void transpose_w(const float* __restrict__ W, int total) {
    int i = blockIdx.x * blockDim.x + threadIdx.x;
    if (i < total) {
        int k = i / (C * C);
        int r = i % (C * C);
        int cin = r / C, cout = r % C;
        g_Wt[k * C * C + cout * C + cin] = W[i];
    }
}

// ---------------- nbr transpose: [N][K] -> [K][N] (tiled, coalesced) ----------------
__global__ void transpose_nbr(const int* __restrict__ nbr, int n, int kt) {
    __shared__ int t[32][33];
    int k0 = blockIdx.y * 32, vb = blockIdx.x * 32;
    int kk = k0 + threadIdx.x;
#pragma unroll
    for (int dy = 0; dy < 32; dy += 8) {
        int v = vb + threadIdx.y + dy;
        if (v < n && kk < kt) t[threadIdx.y + dy][threadIdx.x] = nbr[(size_t)v * kt + kk];
    }
    __syncthreads();
    int vw = vb + threadIdx.x;
#pragma unroll
    for (int dy = 0; dy < 32; dy += 8) {
        int k = k0 + threadIdx.y + dy;
        if (k < kt && vw < n) g_nbrT[(size_t)k * n + vw] = t[threadIdx.x][threadIdx.y + dy];
    }
}

// smem index macros (float offsets)
#define XSTOFF(w_, s_, i_) (((((w_) * NSTG + (s_)) * VW) + (i_)) * C)
#define WSTOFF(s_, r_, c_) ((s_) * C * C + (r_) * C + ((((c_) ^ ((r_) & 7))) << 2))

// ---------------- pipelined sparse conv ----------------
template <int KT>
__global__ __launch_bounds__(256, 3) void conv_pipe(
    const float* __restrict__ x, const float* __restrict__ bconv,
    float* __restrict__ out, int n)
{
    __shared__ __align__(16) float smem[CWARPS * NSTG * VW * C + NSTG * C * C]; // 48KB
    float* xst = smem;
    float* wst = smem + CWARPS * NSTG * VW * C;

    const int tid = threadIdx.x;
    const int warp = tid >> 5, lane = tid & 31;
    const int bi = lane >> 3, cj = lane & 7;
    const int v0 = blockIdx.x * VB + warp * VW;
    const uint32_t xbase = (uint32_t)__cvta_generic_to_shared(xst);
    const uint32_t wbase = (uint32_t)__cvta_generic_to_shared(wst);

    int vv[2]; bool vok[2];
#pragma unroll
    for (int m = 0; m < 2; m++) { vv[m] = v0 + bi + 4 * m; vok[m] = (vv[m] < n); }

    F2U pk; pk.f = make_float2(bconv[lane], 0.f);
    ull acc2[VW];
#pragma unroll
    for (int i = 0; i < VW; i++) acc2[i] = pk.u;

    int nidx[NSTG][2];
    unsigned vmask[NSTG];

    auto FETCH = [&](int tt) {
        int s = tt & (NSTG - 1);
#pragma unroll
        for (int m = 0; m < 2; m++)
            nidx[s][m] = vok[m] ? __ldg(&g_nbrT[(size_t)tt * n + vv[m]]) : -1;
    };
    auto ISSUE = [&](int tt) {
        int s = tt & (NSTG - 1);
        unsigned bits = 0;
#pragma unroll
        for (int m = 0; m < 2; m++) {
            int id = nidx[s][m];
            int i = bi + 4 * m;
            if (id >= 0) {
                bits |= 1u << i;
                cp_async16(xbase + (uint32_t)((XSTOFF(warp, s, i) + cj * 4) * 4),
                           x + (size_t)id * C + cj * 4);
            }
        }
        vmask[s] = __reduce_or_sync(0xffffffffu, bits);
        // stage this tap's 4KB weight tile: each of 256 threads copies one 16B chunk
        cp_async16(wbase + (uint32_t)(WSTOFF(s, tid >> 3, tid & 7) * 4),
                   g_Wt + tt * (C * C) + tid * 4);
    };
    auto COMPUTE = [&](int tt) {
        int s = tt & (NSTG - 1);
        unsigned vm = vmask[s];
#pragma unroll
        for (int i = 0; i < VW; i++) {
            if ((vm >> i) & 1u) {
                ull a = acc2[i];
#pragma unroll
                for (int j = 0; j < 8; j++) {
                    ulonglong2 w2 = *(const ulonglong2*)(wst + WSTOFF(s, lane, j));
                    ulonglong2 x2 = *(const ulonglong2*)(xst + XSTOFF(warp, s, i) + j * 4);
                    a = fma2(x2.x, w2.x, a);
                    a = fma2(x2.y, w2.y, a);
                }
                acc2[i] = a;
            }
        }
    };

    // prologue: interleaved so FETCH(t+4) never clobbers a slot before ISSUE(t) reads it
    FETCH(0); FETCH(1); FETCH(2); FETCH(3);
    ISSUE(0); cp_commit();
    FETCH(4);                    // slot 0: tap 0 already issued
    ISSUE(1); cp_commit();
    FETCH(5);                    // slot 1: tap 1 already issued
    ISSUE(2); cp_commit();

#pragma unroll 4
    for (int t = 0; t < KT; t++) {
        if (t + 6 < KT) FETCH(t + 6);   // slot (t+2)&3: tap t+2 issued at iter t-1/prologue
        cp_wait<2>();            // tap t's gathers + weights (all threads) landed
        __syncthreads();         // weights staged by all threads now visible
        COMPUTE(t);
        if (t + 3 < KT) ISSUE(t + 3);   // writes stage (t-1)&3: all readers passed barrier
        cp_commit();
    }

    // epilogue: store out + fused BN partials (reuse own warp's xst region)
    float s1 = 0.f, s2 = 0.f;
#pragma unroll
    for (int i = 0; i < VW; i++) {
        int v = v0 + i;
        if (v < n) {
            F2U u; u.u = acc2[i];
            float a = u.f.x + u.f.y;
            out[(size_t)v * C + lane] = a;
            s1 += a;
            s2 += a * a;
        }
    }
    xst[warp * (NSTG * VW * C) + lane] = s1;
    xst[warp * (NSTG * VW * C) + C + lane] = s2;
    __syncthreads();
    if (tid < C) {
        float a = 0.f, b2 = 0.f;
#pragma unroll
        for (int w = 0; w < CWARPS; w++) {
            a  += xst[w * (NSTG * VW * C) + tid];
            b2 += xst[w * (NSTG * VW * C) + C + tid];
        }
        g_part[blockIdx.x * 2 * C + tid] = a;
        g_part[blockIdx.x * 2 * C + C + tid] = b2;
    }
}

// ---------------- generic fallback conv ----------------
__global__ __launch_bounds__(256) void conv_generic(
    const float* __restrict__ x, const int* __restrict__ nbr,
    const float* __restrict__ bconv, float* __restrict__ out,
    int n, int kt)
{
    __shared__ __align__(16) float xsm[8][16][C];
    int warp = threadIdx.x >> 5, lane = threadIdx.x & 31;
    int v0 = blockIdx.x * 128 + warp * 16;
    float b = bconv[lane];
    float acc[16];
#pragma unroll
    for (int i = 0; i < 16; i++) acc[i] = b;
    for (int k = 0; k < kt; k++) {
        float4 w[8];
        const float4* wp = (const float4*)(g_Wt + k * C * C + lane * C);
#pragma unroll
        for (int j = 0; j < 8; j++) w[j] = wp[j];
        unsigned vm = 0;
#pragma unroll
        for (int i = 0; i < 16; i++) {
            int v = v0 + i;
            if (v < n) {
                int idx = __ldg(&nbr[(size_t)v * kt + k]);
                if (idx >= 0) { vm |= (1u << i); xsm[warp][i][lane] = x[(size_t)idx * C + lane]; }
            }
        }
        __syncwarp();
#pragma unroll
        for (int i = 0; i < 16; i++) {
            if ((vm >> i) & 1u) {
                const float4* xs = (const float4*)xsm[warp][i];
                float a = acc[i];
#pragma unroll
                for (int j = 0; j < 8; j++) {
                    float4 xv = xs[j];
                    a = fmaf(xv.x, w[j].x, a); a = fmaf(xv.y, w[j].y, a);
                    a = fmaf(xv.z, w[j].z, a); a = fmaf(xv.w, w[j].w, a);
                }
                acc[i] = a;
            }
        }
        __syncwarp();
    }
#pragma unroll
    for (int i = 0; i < 16; i++) {
        int v = v0 + i;
        if (v < n) out[(size_t)v * C + lane] = acc[i];
    }
}

__global__ __launch_bounds__(256) void bn_partial(const float* __restrict__ out, int n) {
    int lane = threadIdx.x & 31, w = threadIdx.x >> 5;
    float s = 0.f, s2 = 0.f;
    for (int r = blockIdx.x * 8 + w; r < n; r += gridDim.x * 8) {
        float v = out[(size_t)r * C + lane];
        s += v; s2 += v * v;
    }
    __shared__ float sh[2][8][C];
    sh[0][w][lane] = s; sh[1][w][lane] = s2;
    __syncthreads();
    if (threadIdx.x < C) {
        float S = 0.f, S2 = 0.f;
#pragma unroll
        for (int j = 0; j < 8; j++) { S += sh[0][j][threadIdx.x]; S2 += sh[1][j][threadIdx.x]; }
        g_part[blockIdx.x * 2 * C + threadIdx.x] = S;
        g_part[blockIdx.x * 2 * C + C + threadIdx.x] = S2;
    }
}

// ---------------- BN final reduce (1024 threads) ----------------
__global__ void bn_final(int n, int nblocks) {
    int lane = threadIdx.x & 31, w = threadIdx.x >> 5;   // 32 warps
    float S = 0.f, S2 = 0.f;
    for (int b = w; b < nblocks; b += 32) {
        S  += g_part[b * 2 * C + lane];
        S2 += g_part[b * 2 * C + C + lane];
    }
    __shared__ float sh[2][32][C];
    sh[0][w][lane] = S; sh[1][w][lane] = S2;
    __syncthreads();
    if (threadIdx.x < C) {
        float a = 0.f, a2 = 0.f;
#pragma unroll
        for (int j = 0; j < 32; j++) { a += sh[0][j][threadIdx.x]; a2 += sh[1][j][threadIdx.x]; }
        float mean = a / (float)n;
        float var = a2 / (float)n - mean * mean;
        g_mean[threadIdx.x] = mean;
        g_rstd[threadIdx.x] = rsqrtf(var + EPSBN);
    }
}

// ---------------- BN apply + ELU + linear (4 voxels/warp-iter, f32x2) ----------------
__global__ __launch_bounds__(256) void apply_kernel(
    const float* __restrict__ gamma, const float* __restrict__ beta,
    const float* __restrict__ Wlin, const float* __restrict__ blin,
    float* __restrict__ out, int n)
{
    __shared__ __align__(16) float ysm[8][4][C];
    int lane = threadIdx.x & 31, w = threadIdx.x >> 5;
    float m = g_mean[lane], rs = g_rstd[lane];
    float ga = gamma[lane], be = beta[lane];
    F2U blu; blu.f = make_float2(blin[lane], 0.f);

    ull wl[16];
    const ull* wp = (const ull*)(Wlin + lane * C);
#pragma unroll
    for (int p = 0; p < 16; p++) wl[p] = wp[p];

    for (int v4 = (blockIdx.x * 8 + w) * 4; v4 < n; v4 += gridDim.x * 32) {
        float y[4];
#pragma unroll
        for (int q = 0; q < 4; q++) {
            int v = v4 + q;
            float o = (v < n) ? out[(size_t)v * C + lane] : 0.f;
            float t = fmaf((o - m) * rs, ga, be);
            y[q] = (t > 0.f) ? t : expm1f(t);
            ysm[w][q][lane] = y[q];
        }
        __syncwarp();
#pragma unroll
        for (int q = 0; q < 4; q++) {
            int v = v4 + q;
            if (v < n) {
                const ull* ys = (const ull*)ysm[w][q];
                ull z2 = blu.u;
#pragma unroll
                for (int p = 0; p < 16; p++) z2 = fma2(ys[p], wl[p], z2);
                F2U r; r.u = z2;
                out[(size_t)v * C + lane] = r.f.x + r.f.y;
            }
        }
        __syncwarp();
    }
}

extern "C" void kernel_launch(void* const* d_in, const int* in_sizes, int n_in,
                              void* d_out, int out_size)
{
    const float* x     = (const float*)d_in[0];
    const int*   nbr   = (const int*)d_in[1];
    const float* Wc    = (const float*)d_in[2];
    const float* bc    = (const float*)d_in[3];
    const float* gamma = (const float*)d_in[4];
    const float* beta  = (const float*)d_in[5];
    const float* Wl    = (const float*)d_in[6];
    const float* bl    = (const float*)d_in[7];
    float* out = (float*)d_out;

    int n  = in_sizes[0] / C;
    int kt = in_sizes[1] / n;
    int wtot = in_sizes[2];

    transpose_w<<<(wtot + 255) / 256, 256>>>(Wc, wtot);

    int nb = (n + VB - 1) / VB;
    if (kt == KTAP && n <= MAXN && nb <= MAXBLK) {
        dim3 tg((n + 31) / 32, (kt + 31) / 32);
        transpose_nbr<<<tg, dim3(32, 8)>>>(nbr, n, kt);
        conv_pipe<KTAP><<<nb, 256>>>(x, bc, out, n);
        bn_final<<<1, 1024>>>(n, nb);
    } else {
        conv_generic<<<(n + 127) / 128, 256>>>(x, nbr, bc, out, n, kt);
        bn_partial<<<512, 256>>>(out, n);
        bn_final<<<1, 1024>>>(n, 512);
    }
    apply_kernel<<<2048, 256>>>(gamma, beta, Wl, bl, out, n);
}

// round 7
// speedup vs baseline: 3.3880x; 1.3284x over previous
#include <cuda_runtime.h>
#include <cstdint>

#define C 32
#define EPSBN 1e-5f

#define CWARPS 4
#define VW 16
#define VB (CWARPS * VW)      // 64 voxels / block
#define NSTG 4                // stage ring
#define MAXBLK 8192
#define MAXN 500000
#define KTAP 125

typedef unsigned long long ull;

// ---- device scratch (no allocations allowed) ----
__device__ __align__(16) float g_Wt[KTAP * C * C];    // [K][COUT][CIN]
__device__ int   g_nbrT[(size_t)KTAP * MAXN];         // [K][N] transposed indices
__device__ float g_part[MAXBLK * 2 * C];
__device__ float g_mean[C];
__device__ float g_rstd[C];

// ---- helpers ----
__device__ __forceinline__ void cp_async16(uint32_t dst, const void* src) {
    asm volatile("cp.async.cg.shared.global [%0], [%1], 16;" :: "r"(dst), "l"(src));
}
__device__ __forceinline__ void cp_commit() { asm volatile("cp.async.commit_group;"); }
template <int N_> __device__ __forceinline__ void cp_wait() {
    asm volatile("cp.async.wait_group %0;" :: "n"(N_));
}
__device__ __forceinline__ ull fma2(ull a, ull b, ull c) {
    ull d;
    asm("fma.rn.f32x2 %0, %1, %2, %3;" : "=l"(d) : "l"(a), "l"(b), "l"(c));
    return d;
}
union F2U { float2 f; ull u; };

// ---------------- W transpose: [K][CIN][COUT] -> [K][COUT][CIN] ----------------
__global__ void transpose_w(const float* __restrict__ W, int total) {
    int i = blockIdx.x * blockDim.x + threadIdx.x;
    if (i < total) {
        int k = i / (C * C);
        int r = i % (C * C);
        int cin = r / C, cout = r % C;
        g_Wt[k * C * C + cout * C + cin] = W[i];
    }
}

// ---------------- nbr transpose: [N][K] -> [K][N] (tiled, coalesced) ----------------
__global__ void transpose_nbr(const int* __restrict__ nbr, int n, int kt) {
    __shared__ int t[32][33];
    int k0 = blockIdx.y * 32, vb = blockIdx.x * 32;
    int kk = k0 + threadIdx.x;
#pragma unroll
    for (int dy = 0; dy < 32; dy += 8) {
        int v = vb + threadIdx.y + dy;
        if (v < n && kk < kt) t[threadIdx.y + dy][threadIdx.x] = nbr[(size_t)v * kt + kk];
    }
    __syncthreads();
    int vw = vb + threadIdx.x;
#pragma unroll
    for (int dy = 0; dy < 32; dy += 8) {
        int k = k0 + threadIdx.y + dy;
        if (k < kt && vw < n) g_nbrT[(size_t)k * n + vw] = t[threadIdx.x][threadIdx.y + dy];
    }
}

// smem index macros (float offsets)
#define XSTOFF(w_, s_, i_) (((((w_) * NSTG + (s_)) * VW) + (i_)) * C)
#define WSTOFF(s_, r_, c_) ((s_) * C * C + (r_) * C + ((((c_) ^ ((r_) & 7))) << 2))

// ---------------- pipelined sparse conv ----------------
template <int KT>
__global__ __launch_bounds__(128, 4) void conv_pipe(
    const float* __restrict__ x, const float* __restrict__ bconv,
    float* __restrict__ out, int n)
{
    __shared__ __align__(16) float smem[CWARPS * NSTG * VW * C + NSTG * C * C]; // 48KB
    float* xst = smem;
    float* wst = smem + CWARPS * NSTG * VW * C;

    const int tid = threadIdx.x;
    const int warp = tid >> 5, lane = tid & 31;
    const int bi = lane >> 3, cj = lane & 7;
    const int v0 = blockIdx.x * VB + warp * VW;
    const uint32_t xbase = (uint32_t)__cvta_generic_to_shared(xst);
    const uint32_t wbase = (uint32_t)__cvta_generic_to_shared(wst);

    int vv[4]; bool vok[4];
#pragma unroll
    for (int m = 0; m < 4; m++) { vv[m] = v0 + bi + 4 * m; vok[m] = (vv[m] < n); }

    F2U pk; pk.f = make_float2(bconv[lane], 0.f);
    ull acc2[VW];
#pragma unroll
    for (int i = 0; i < VW; i++) acc2[i] = pk.u;

    int nidx[NSTG][4];
    unsigned vmask[NSTG];

    auto FETCH = [&](int tt) {
        int s = tt & (NSTG - 1);
#pragma unroll
        for (int m = 0; m < 4; m++)
            nidx[s][m] = vok[m] ? __ldg(&g_nbrT[(size_t)tt * n + vv[m]]) : -1;
    };
    auto ISSUE = [&](int tt) {
        int s = tt & (NSTG - 1);
        unsigned bits = 0;
#pragma unroll
        for (int m = 0; m < 4; m++) {
            int id = nidx[s][m];
            int i = bi + 4 * m;
            if (id >= 0) {
                bits |= 1u << i;
                cp_async16(xbase + (uint32_t)((XSTOFF(warp, s, i) + cj * 4) * 4),
                           x + (size_t)id * C + cj * 4);
            }
        }
        vmask[s] = __reduce_or_sync(0xffffffffu, bits);
        // stage this tap's 4KB weight tile: 128 threads copy 2x16B chunks each
#pragma unroll
        for (int h = 0; h < 2; h++) {
            int c0 = tid + h * 128;                // chunk index 0..255
            cp_async16(wbase + (uint32_t)(WSTOFF(s, c0 >> 3, c0 & 7) * 4),
                       g_Wt + tt * (C * C) + c0 * 4);
        }
    };
    auto COMPUTE = [&](int tt) {
        int s = tt & (NSTG - 1);
        unsigned vm = vmask[s];
        if (vm) {
            // weights for this tap, once per warp: lane's 128B row into regs
            ulonglong2 w2[8];
#pragma unroll
            for (int j = 0; j < 8; j++)
                w2[j] = *(const ulonglong2*)(wst + WSTOFF(s, lane, j));
#pragma unroll
            for (int i = 0; i < VW; i++) {
                if ((vm >> i) & 1u) {
                    ull a = acc2[i];
#pragma unroll
                    for (int j = 0; j < 8; j++) {
                        ulonglong2 x2 = *(const ulonglong2*)(xst + XSTOFF(warp, s, i) + j * 4);
                        a = fma2(x2.x, w2[j].x, a);
                        a = fma2(x2.y, w2[j].y, a);
                    }
                    acc2[i] = a;
                }
            }
        }
    };

    // prologue: interleaved so FETCH(t+4) never clobbers a slot before ISSUE(t) reads it
    FETCH(0); FETCH(1); FETCH(2); FETCH(3);
    ISSUE(0); cp_commit();
    FETCH(4);                    // slot 0: tap 0 already issued
    ISSUE(1); cp_commit();
    FETCH(5);                    // slot 1: tap 1 already issued
    ISSUE(2); cp_commit();

#pragma unroll 4
    for (int t = 0; t < KT; t++) {
        if (t + 6 < KT) FETCH(t + 6);   // slot (t+2)&3: tap t+2 issued at iter t-1/prologue
        cp_wait<2>();            // tap t's gathers + weights (all threads) landed
        __syncthreads();         // weights staged by all threads now visible
        COMPUTE(t);
        if (t + 3 < KT) ISSUE(t + 3);   // writes stage (t-1)&3: all readers passed barrier
        cp_commit();
    }

    // epilogue: store out + fused BN partials (reuse own warp's xst region)
    float s1 = 0.f, s2 = 0.f;
#pragma unroll
    for (int i = 0; i < VW; i++) {
        int v = v0 + i;
        if (v < n) {
            F2U u; u.u = acc2[i];
            float a = u.f.x + u.f.y;
            out[(size_t)v * C + lane] = a;
            s1 += a;
            s2 += a * a;
        }
    }
    __syncthreads();             // all COMPUTE smem reads done before reuse
    xst[warp * (NSTG * VW * C) + lane] = s1;
    xst[warp * (NSTG * VW * C) + C + lane] = s2;
    __syncthreads();
    if (tid < C) {
        float a = 0.f, b2 = 0.f;
#pragma unroll
        for (int w = 0; w < CWARPS; w++) {
            a  += xst[w * (NSTG * VW * C) + tid];
            b2 += xst[w * (NSTG * VW * C) + C + tid];
        }
        g_part[blockIdx.x * 2 * C + tid] = a;
        g_part[blockIdx.x * 2 * C + C + tid] = b2;
    }
}

// ---------------- generic fallback conv ----------------
__global__ __launch_bounds__(256) void conv_generic(
    const float* __restrict__ x, const int* __restrict__ nbr,
    const float* __restrict__ bconv, float* __restrict__ out,
    int n, int kt)
{
    __shared__ __align__(16) float xsm[8][16][C];
    int warp = threadIdx.x >> 5, lane = threadIdx.x & 31;
    int v0 = blockIdx.x * 128 + warp * 16;
    float b = bconv[lane];
    float acc[16];
#pragma unroll
    for (int i = 0; i < 16; i++) acc[i] = b;
    for (int k = 0; k < kt; k++) {
        float4 w[8];
        const float4* wp = (const float4*)(g_Wt + k * C * C + lane * C);
#pragma unroll
        for (int j = 0; j < 8; j++) w[j] = wp[j];
        unsigned vm = 0;
#pragma unroll
        for (int i = 0; i < 16; i++) {
            int v = v0 + i;
            if (v < n) {
                int idx = __ldg(&nbr[(size_t)v * kt + k]);
                if (idx >= 0) { vm |= (1u << i); xsm[warp][i][lane] = x[(size_t)idx * C + lane]; }
            }
        }
        __syncwarp();
#pragma unroll
        for (int i = 0; i < 16; i++) {
            if ((vm >> i) & 1u) {
                const float4* xs = (const float4*)xsm[warp][i];
                float a = acc[i];
#pragma unroll
                for (int j = 0; j < 8; j++) {
                    float4 xv = xs[j];
                    a = fmaf(xv.x, w[j].x, a); a = fmaf(xv.y, w[j].y, a);
                    a = fmaf(xv.z, w[j].z, a); a = fmaf(xv.w, w[j].w, a);
                }
                acc[i] = a;
            }
        }
        __syncwarp();
    }
#pragma unroll
    for (int i = 0; i < 16; i++) {
        int v = v0 + i;
        if (v < n) out[(size_t)v * C + lane] = acc[i];
    }
}

__global__ __launch_bounds__(256) void bn_partial(const float* __restrict__ out, int n) {
    int lane = threadIdx.x & 31, w = threadIdx.x >> 5;
    float s = 0.f, s2 = 0.f;
    for (int r = blockIdx.x * 8 + w; r < n; r += gridDim.x * 8) {
        float v = out[(size_t)r * C + lane];
        s += v; s2 += v * v;
    }
    __shared__ float sh[2][8][C];
    sh[0][w][lane] = s; sh[1][w][lane] = s2;
    __syncthreads();
    if (threadIdx.x < C) {
        float S = 0.f, S2 = 0.f;
#pragma unroll
        for (int j = 0; j < 8; j++) { S += sh[0][j][threadIdx.x]; S2 += sh[1][j][threadIdx.x]; }
        g_part[blockIdx.x * 2 * C + threadIdx.x] = S;
        g_part[blockIdx.x * 2 * C + C + threadIdx.x] = S2;
    }
}

// ---------------- BN final reduce (1024 threads) ----------------
__global__ void bn_final(int n, int nblocks) {
    int lane = threadIdx.x & 31, w = threadIdx.x >> 5;   // 32 warps
    float S = 0.f, S2 = 0.f;
    for (int b = w; b < nblocks; b += 32) {
        S  += g_part[b * 2 * C + lane];
        S2 += g_part[b * 2 * C + C + lane];
    }
    __shared__ float sh[2][32][C];
    sh[0][w][lane] = S; sh[1][w][lane] = S2;
    __syncthreads();
    if (threadIdx.x < C) {
        float a = 0.f, a2 = 0.f;
#pragma unroll
        for (int j = 0; j < 32; j++) { a += sh[0][j][threadIdx.x]; a2 += sh[1][j][threadIdx.x]; }
        float mean = a / (float)n;
        float var = a2 / (float)n - mean * mean;
        g_mean[threadIdx.x] = mean;
        g_rstd[threadIdx.x] = rsqrtf(var + EPSBN);
    }
}

// ---------------- BN apply + ELU + linear (4 voxels/warp-iter, f32x2) ----------------
__global__ __launch_bounds__(256) void apply_kernel(
    const float* __restrict__ gamma, const float* __restrict__ beta,
    const float* __restrict__ Wlin, const float* __restrict__ blin,
    float* __restrict__ out, int n)
{
    __shared__ __align__(16) float ysm[8][4][C];
    int lane = threadIdx.x & 31, w = threadIdx.x >> 5;
    float m = g_mean[lane], rs = g_rstd[lane];
    float ga = gamma[lane], be = beta[lane];
    F2U blu; blu.f = make_float2(blin[lane], 0.f);

    ull wl[16];
    const ull* wp = (const ull*)(Wlin + lane * C);
#pragma unroll
    for (int p = 0; p < 16; p++) wl[p] = wp[p];

    for (int v4 = (blockIdx.x * 8 + w) * 4; v4 < n; v4 += gridDim.x * 32) {
        float y[4];
#pragma unroll
        for (int q = 0; q < 4; q++) {
            int v = v4 + q;
            float o = (v < n) ? out[(size_t)v * C + lane] : 0.f;
            float t = fmaf((o - m) * rs, ga, be);
            y[q] = (t > 0.f) ? t : expm1f(t);
            ysm[w][q][lane] = y[q];
        }
        __syncwarp();
#pragma unroll
        for (int q = 0; q < 4; q++) {
            int v = v4 + q;
            if (v < n) {
                const ull* ys = (const ull*)ysm[w][q];
                ull z2 = blu.u;
#pragma unroll
                for (int p = 0; p < 16; p++) z2 = fma2(ys[p], wl[p], z2);
                F2U r; r.u = z2;
                out[(size_t)v * C + lane] = r.f.x + r.f.y;
            }
        }
        __syncwarp();
    }
}

extern "C" void kernel_launch(void* const* d_in, const int* in_sizes, int n_in,
                              void* d_out, int out_size)
{
    const float* x     = (const float*)d_in[0];
    const int*   nbr   = (const int*)d_in[1];
    const float* Wc    = (const float*)d_in[2];
    const float* bc    = (const float*)d_in[3];
    const float* gamma = (const float*)d_in[4];
    const float* beta  = (const float*)d_in[5];
    const float* Wl    = (const float*)d_in[6];
    const float* bl    = (const float*)d_in[7];
    float* out = (float*)d_out;

    int n  = in_sizes[0] / C;
    int kt = in_sizes[1] / n;
    int wtot = in_sizes[2];

    transpose_w<<<(wtot + 255) / 256, 256>>>(Wc, wtot);

    int nb = (n + VB - 1) / VB;
    if (kt == KTAP && n <= MAXN && nb <= MAXBLK) {
        dim3 tg((n + 31) / 32, (kt + 31) / 32);
        transpose_nbr<<<tg, dim3(32, 8)>>>(nbr, n, kt);
        conv_pipe<KTAP><<<nb, 128>>>(x, bc, out, n);
        bn_final<<<1, 1024>>>(n, nb);
    } else {
        conv_generic<<<(n + 127) / 128, 256>>>(x, nbr, bc, out, n, kt);
        bn_partial<<<512, 256>>>(out, n);
        bn_final<<<1, 1024>>>(n, 512);
    }
    apply_kernel<<<2048, 256>>>(gamma, beta, Wl, bl, out, n);
}